// round 5
// baseline (speedup 1.0000x reference)
#include <cuda_runtime.h>
#include <cstdint>

#define B_ROWS  32768
#define D_DIM   256
#define K_CODES 2048

// output layout (float32): quantized_st[B*D], vq_loss, entropy, inds[B], cluster_metric
#define OFF_VQ  8388608
#define OFF_ENT 8388609
#define OFF_IND 8388610
#define OFF_CL  8421378

#define TIE_EPS 8e-4f

// ---------------- device scratch ----------------
__device__ uint32_t g_xq[B_ROWS * 64];    // [256 panels][64 k'][128 rows] packed s8x4
__device__ uint32_t g_eq[K_CODES * 64];   // [16 panels][64 k'][128 cols]
__device__ float g_xsq[B_ROWS];
__device__ float g_cscale[B_ROWS];        // 2 * s_row * t_e
__device__ float g_esq[K_CODES];
__device__ int   g_ind[B_ROWS];
__device__ int   g_flag[B_ROWS];
__device__ float g_cl_val[B_ROWS];
__device__ int   g_counts[K_CODES];
__device__ float g_mse_part[8192];

// ---------------- helpers ----------------
__device__ __forceinline__ uint32_t smem_to_u32(const void* p) {
    uint32_t a;
    asm("{ .reg .u64 t; cvta.to.shared.u64 t, %1; cvt.u32.u64 %0, t; }"
        : "=r"(a) : "l"(p));
    return a;
}
__device__ __forceinline__ void cpa16(uint32_t dst, const void* src) {
    asm volatile("cp.async.cg.shared.global [%0], [%1], 16;"
        :: "r"(dst), "l"((unsigned long long)__cvta_generic_to_global(src)) : "memory");
}
#define CP_COMMIT() asm volatile("cp.async.commit_group;" ::: "memory")
#define CP_WAIT1()  asm volatile("cp.async.wait_group 1;" ::: "memory")

// two-smallest tracking with first-index tie-break (matches jnp.argmin)
__device__ __forceinline__ void upd1(float& b, float& b2, int& i, float v, int n) {
    if (v < b || (v == b && n < i)) { b2 = b; b = v; i = n; }
    else b2 = fminf(b2, v);
}
__device__ __forceinline__ void merge2(float& b, float& b2, int& i,
                                       float ob, float ob2, int oi) {
    if (ob < b || (ob == b && oi < i)) { b2 = fminf(b, ob2); b = ob; i = oi; }
    else b2 = fminf(b2, ob);
}
__device__ __forceinline__ uint32_t pack4(float a, float b, float c, float d, float inv) {
    int q0 = __float2int_rn(a * inv), q1 = __float2int_rn(b * inv);
    int q2 = __float2int_rn(c * inv), q3 = __float2int_rn(d * inv);
    return (uint32_t)(q0 & 0xff) | ((uint32_t)(q1 & 0xff) << 8)
         | ((uint32_t)(q2 & 0xff) << 16) | ((uint32_t)(q3 & 0xff) << 24);
}

// ---------------- quantize: fp32 -> per-row-scaled s8, transposed panels ----------------
// blocks 0..255: latent panels; 256..271: embedding panels. Also emits xsq/esq/cscale.
__global__ void vq_quant_kernel(const float* __restrict__ latents,
                                const float* __restrict__ embedding) {
    __shared__ uint32_t Qs[64 * 129];
    const int tid = threadIdx.x;
    const int w = tid >> 5, lane = tid & 31;
    const bool isE = blockIdx.x >= 256;
    const int p = isE ? (int)blockIdx.x - 256 : (int)blockIdx.x;
    const float* src = isE ? embedding : latents;

    if (blockIdx.x == 0)
        for (int k = tid; k < K_CODES; k += 256) g_counts[k] = 0;

    for (int it = 0; it < 16; it++) {
        const int rl = it * 8 + w;
        const int row = p * 128 + rl;
        const float4* pr = (const float4*)(src + (size_t)row * D_DIM);
        const float4 f0 = pr[lane];
        const float4 f1 = pr[lane + 32];

        float ss = f0.x*f0.x + f0.y*f0.y + f0.z*f0.z + f0.w*f0.w
                 + f1.x*f1.x + f1.y*f1.y + f1.z*f1.z + f1.w*f1.w;
        float mx = fmaxf(fmaxf(fmaxf(fabsf(f0.x), fabsf(f0.y)), fmaxf(fabsf(f0.z), fabsf(f0.w))),
                         fmaxf(fmaxf(fabsf(f1.x), fabsf(f1.y)), fmaxf(fabsf(f1.z), fabsf(f1.w))));
#pragma unroll
        for (int off = 16; off; off >>= 1) {
            ss += __shfl_xor_sync(0xffffffffu, ss, off);
            mx = fmaxf(mx, __shfl_xor_sync(0xffffffffu, mx, off));
        }

        float inv;
        if (isE) {
            inv = 2048.0f * 127.0f;
            if (lane == 0) g_esq[row] = ss;
        } else {
            inv = 127.0f / fmaxf(mx, 1e-30f);
            if (lane == 0) {
                g_xsq[row] = ss;
                g_cscale[row] = mx * (2.0f / (127.0f * 127.0f * 2048.0f));
            }
        }
        Qs[lane * 129 + rl]        = pack4(f0.x, f0.y, f0.z, f0.w, inv);
        Qs[(lane + 32) * 129 + rl] = pack4(f1.x, f1.y, f1.z, f1.w, inv);
    }
    __syncthreads();

    uint32_t* dst = (isE ? g_eq : g_xq) + (size_t)p * 8192;
#pragma unroll
    for (int i = 0; i < 32; i++) {
        const int o = i * 256 + tid;
        dst[o] = Qs[o + (o >> 7)];
    }
}

// ---------------- main: dp4a int8 GEMM + fused argmin ----------------
#define SMEM_TOTAL 98304   // A 32KB + B 2x32KB

__global__ void __launch_bounds__(256, 1)
vq_main_kernel(float* __restrict__ out) {
    extern __shared__ uint32_t sm[];
    const uint32_t smb = smem_to_u32(sm);

    const int tid  = threadIdx.x;
    const int r    = tid >> 4;     // 0..15: rows r*8..r*8+7
    const int c    = tid & 15;     // 0..15: cols c*8..c*8+7 (within jn tile)
    const int lane = tid & 31;
    const int row0 = blockIdx.x * 128;

    // A tile: contiguous 32KB panel
    {
        const char* gA = (const char*)(g_xq + (size_t)blockIdx.x * 8192);
#pragma unroll
        for (int i = 0; i < 8; i++)
            cpa16(smb + (tid + i * 256) * 16, gA + (tid + i * 256) * 16);
    }
    CP_COMMIT();

    auto loadB = [&](int jn) {
        const char* gB = (const char*)(g_eq + (size_t)jn * 8192);
        const uint32_t db = smb + 32768 + (jn & 1) * 32768;
#pragma unroll
        for (int i = 0; i < 8; i++)
            cpa16(db + (tid + i * 256) * 16, gB + (tid + i * 256) * 16);
    };
    loadB(0); CP_COMMIT();
    loadB(1); CP_COMMIT();

    float cr[8];
#pragma unroll
    for (int i = 0; i < 8; i++) cr[i] = g_cscale[row0 + r * 8 + i];

    float rb[8], rb2[8];
    int   ri[8];
#pragma unroll
    for (int i = 0; i < 8; i++) { rb[i] = 3.0e38f; rb2[i] = 3.0e38f; ri[i] = 0; }

    const uint32_t* smA = sm;

    for (int jn = 0; jn < 16; jn++) {
        CP_WAIT1();
        __syncthreads();
        const uint32_t* smB = sm + 8192 + (jn & 1) * 8192;

        int acc[8][8];
#pragma unroll
        for (int i = 0; i < 8; i++)
#pragma unroll
            for (int j = 0; j < 8; j++) acc[i][j] = 0;

#pragma unroll 4
        for (int k = 0; k < 64; k++) {
            const uint4 a0 = *(const uint4*)&smA[k * 128 + r * 8];
            const uint4 a1 = *(const uint4*)&smA[k * 128 + r * 8 + 4];
            const uint4 b0 = *(const uint4*)&smB[k * 128 + c * 8];
            const uint4 b1 = *(const uint4*)&smB[k * 128 + c * 8 + 4];
            const int av[8] = {(int)a0.x, (int)a0.y, (int)a0.z, (int)a0.w,
                               (int)a1.x, (int)a1.y, (int)a1.z, (int)a1.w};
            const int bv[8] = {(int)b0.x, (int)b0.y, (int)b0.z, (int)b0.w,
                               (int)b1.x, (int)b1.y, (int)b1.z, (int)b1.w};
#pragma unroll
            for (int i = 0; i < 8; i++)
#pragma unroll
                for (int j = 0; j < 8; j++)
                    acc[i][j] = __dp4a(av[i], bv[j], acc[i][j]);
        }
        __syncthreads();
        if (jn < 14) loadB(jn + 2);
        CP_COMMIT();

        // epilogue: relative scores (esq - 2*s*t*I), running two-smallest
        const int n0 = jn * 128 + c * 8;
        const float4 e0 = *(const float4*)(g_esq + n0);
        const float4 e1 = *(const float4*)(g_esq + n0 + 4);
        const float ev[8] = {e0.x, e0.y, e0.z, e0.w, e1.x, e1.y, e1.z, e1.w};
#pragma unroll
        for (int j = 0; j < 8; j++)
#pragma unroll
            for (int i = 0; i < 8; i++) {
                const float sc = fmaf(-cr[i], (float)acc[i][j], ev[j]);
                upd1(rb[i], rb2[i], ri[i], sc, n0 + j);
            }
    }

    // merge across the 16 c-threads sharing each row (lane bits 0..3)
#pragma unroll
    for (int i = 0; i < 8; i++)
#pragma unroll
        for (int m = 1; m <= 8; m <<= 1) {
            const float ob  = __shfl_xor_sync(0xffffffffu, rb[i],  m);
            const float ob2 = __shfl_xor_sync(0xffffffffu, rb2[i], m);
            const int   oi  = __shfl_xor_sync(0xffffffffu, ri[i],  m);
            merge2(rb[i], rb2[i], ri[i], ob, ob2, oi);
        }

    if ((lane & 15) == 0) {
#pragma unroll
        for (int i = 0; i < 8; i++) {
            const int row = row0 + r * 8 + i;
            g_ind[row] = ri[i];
            out[OFF_IND + row] = (float)ri[i];
            g_cl_val[row] = g_xsq[row] + rb[i];
            g_flag[row] = (rb2[i] - rb[i] < TIE_EPS) ? 1 : 0;
        }
    }
}

// ---------------- fixup: exact fp32 recompute of ambiguous rows ----------------
__global__ void vq_fixup_kernel(const float* __restrict__ latents,
                                const float* __restrict__ embedding,
                                float* __restrict__ out) {
    __shared__ float lx[256];
    __shared__ float sv[256];
    __shared__ int   si[256];
    const int tid = threadIdx.x;
    const int rbeg = blockIdx.x * 256;

    for (int rr = rbeg; rr < rbeg + 256; rr++) {
        if (!g_flag[rr]) continue;

        lx[tid] = latents[(size_t)rr * D_DIM + tid];
        __syncthreads();
        const float xq = g_xsq[rr];
        float bb = 3.0e38f;
        int bi = 0x7fffffff;
#pragma unroll
        for (int cc = 0; cc < 8; cc++) {
            const int cI = cc * 256 + tid;
            const float* e = embedding + (size_t)cI * D_DIM;
            float dot = 0.0f;
#pragma unroll 8
            for (int k = 0; k < D_DIM; k++) dot = fmaf(e[k], lx[k], dot);
            const float sc = (xq + g_esq[cI]) - 2.0f * dot;
            if (sc < bb || (sc == bb && cI < bi)) { bb = sc; bi = cI; }
        }
        sv[tid] = bb; si[tid] = bi;
        __syncthreads();
        for (int o = 128; o; o >>= 1) {
            if (tid < o) {
                const float v2 = sv[tid + o]; const int i2 = si[tid + o];
                if (v2 < sv[tid] || (v2 == sv[tid] && i2 < si[tid])) { sv[tid] = v2; si[tid] = i2; }
            }
            __syncthreads();
        }
        if (tid == 0) {
            g_ind[rr] = si[0];
            out[OFF_IND + rr] = (float)si[0];
            g_cl_val[rr] = sv[0];
        }
        __syncthreads();
    }
}

// ---------------- gather + straight-through + mse partials + histogram ----------------
__global__ void vq_gather_kernel(const float* __restrict__ latents,
                                 const float* __restrict__ embedding,
                                 float* __restrict__ out) {
    const int i4 = blockIdx.x * blockDim.x + threadIdx.x;   // float4 index
    const int b  = i4 >> 6;
    const int d  = (i4 & 63) << 2;
    const int ind = g_ind[b];

    if ((i4 & 63) == 0) atomicAdd(&g_counts[ind], 1);

    const float4 q = *reinterpret_cast<const float4*>(embedding + (size_t)ind * D_DIM + d);
    const float4 x = *reinterpret_cast<const float4*>(latents + (size_t)b * D_DIM + d);

    const float dx = q.x - x.x, dy = q.y - x.y, dz = q.z - x.z, dw = q.w - x.w;
    float4 o;
    o.x = x.x + dx; o.y = x.y + dy; o.z = x.z + dz; o.w = x.w + dw;
    *reinterpret_cast<float4*>(out + (size_t)i4 * 4) = o;

    float ss = dx*dx + dy*dy + dz*dz + dw*dw;
#pragma unroll
    for (int off = 16; off; off >>= 1)
        ss += __shfl_down_sync(0xffffffffu, ss, off);

    __shared__ float w[8];
    const int lane = threadIdx.x & 31;
    const int warp = threadIdx.x >> 5;
    if (lane == 0) w[warp] = ss;
    __syncthreads();
    if (threadIdx.x == 0) {
        float t = 0.0f;
        for (int i = 0; i < 8; i++) t += w[i];
        g_mse_part[blockIdx.x] = t;
    }
}

// ---------------- finalize scalars ----------------
__global__ void vq_finalize_kernel(float* __restrict__ out) {
    __shared__ float sh[256];
    const int tid = threadIdx.x;

    float s = 0.0f;
    for (int i = tid; i < 8192; i += 256) s += g_mse_part[i];
    sh[tid] = s; __syncthreads();
    for (int o = 128; o; o >>= 1) { if (tid < o) sh[tid] += sh[tid + o]; __syncthreads(); }
    const float mse_sum = sh[0];
    __syncthreads();

    s = 0.0f;
    for (int i = tid; i < B_ROWS; i += 256) s += g_cl_val[i];
    sh[tid] = s; __syncthreads();
    for (int o = 128; o; o >>= 1) { if (tid < o) sh[tid] += sh[tid + o]; __syncthreads(); }
    const float cl_sum = sh[0];
    __syncthreads();

    s = 0.0f;
    for (int k = tid; k < K_CODES; k += 256) {
        const float p = (float)g_counts[k] * (1.0f / 32768.0f);
        s += p * logf(p + 1e-10f);
    }
    sh[tid] = s; __syncthreads();
    for (int o = 128; o; o >>= 1) { if (tid < o) sh[tid] += sh[tid + o]; __syncthreads(); }

    if (tid == 0) {
        const float m = mse_sum / 8388608.0f;
        out[OFF_VQ]  = m * 0.25f + m;
        out[OFF_ENT] = -sh[0];
        out[OFF_CL]  = cl_sum / 32768.0f;
    }
}

extern "C" void kernel_launch(void* const* d_in, const int* in_sizes, int n_in,
                              void* d_out, int out_size) {
    const float* latents   = (const float*)d_in[0];
    const float* embedding = (const float*)d_in[1];
    float* out = (float*)d_out;

    cudaFuncSetAttribute(vq_main_kernel,
                         cudaFuncAttributeMaxDynamicSharedMemorySize, SMEM_TOTAL);

    vq_quant_kernel<<<272, 256>>>(latents, embedding);
    vq_main_kernel<<<B_ROWS / 128, 256, SMEM_TOTAL>>>(out);
    vq_fixup_kernel<<<B_ROWS / 256, 256>>>(latents, embedding, out);
    vq_gather_kernel<<<(B_ROWS * D_DIM) / (256 * 4), 256>>>(latents, embedding, out);
    vq_finalize_kernel<<<1, 256>>>(out);
}

// round 6
// speedup vs baseline: 2.3553x; 2.3553x over previous
#include <cuda_runtime.h>
#include <cuda_fp16.h>
#include <cstdint>

#define B_ROWS  32768
#define D_DIM   256
#define K_CODES 2048

// output layout (float32): quantized_st[B*D], vq_loss, entropy, inds[B], cluster_metric
#define OFF_VQ  8388608
#define OFF_ENT 8388609
#define OFF_IND 8388610
#define OFF_CL  8421378

#define TIE_EPS 2.5e-4f
#define CS      9.765625e-4f   // 2/2048: unscale for e pre-scaled by 2048

// ---------------- device scratch ----------------
__device__ __half g_xh[B_ROWS * D_DIM];   // [256 panels][256 d][128 m]  (unscaled)
__device__ __half g_eh[K_CODES * D_DIM];  // [16 panels][256 d][128 n]   (scaled x2048)
__device__ float g_xsq[B_ROWS];
__device__ float g_esq[K_CODES];
__device__ int   g_ind[B_ROWS];
__device__ int   g_flag[B_ROWS];
__device__ float g_cl_val[B_ROWS];
__device__ int   g_counts[K_CODES];
__device__ float g_mse_part[8192];

// ---------------- helpers ----------------
__device__ __forceinline__ uint32_t smem_to_u32(const void* p) {
    uint32_t a;
    asm("{ .reg .u64 t; cvta.to.shared.u64 t, %1; cvt.u32.u64 %0, t; }"
        : "=r"(a) : "l"(p));
    return a;
}
__device__ __forceinline__ void cpa16(uint32_t dst, const void* src) {
    asm volatile("cp.async.cg.shared.global [%0], [%1], 16;"
        :: "r"(dst), "l"((unsigned long long)__cvta_generic_to_global(src)) : "memory");
}
#define CP_COMMIT() asm volatile("cp.async.commit_group;" ::: "memory")
#define CP_WAIT1()  asm volatile("cp.async.wait_group 1;" ::: "memory")

__device__ __forceinline__ __half2 u32h2(uint32_t v) {
    __half2 h; *reinterpret_cast<uint32_t*>(&h) = v; return h;
}

// two-smallest tracking with first-index tie-break (matches jnp.argmin)
__device__ __forceinline__ void upd1(float& b, float& b2, int& i, float v, int n) {
    if (v < b || (v == b && n < i)) { b2 = b; b = v; i = n; }
    else b2 = fminf(b2, v);
}
__device__ __forceinline__ void merge2(float& b, float& b2, int& i,
                                       float ob, float ob2, int oi) {
    if (ob < b || (ob == b && oi < i)) { b2 = fminf(b, ob2); b = ob; i = oi; }
    else b2 = fminf(b2, ob);
}

// ---------------- convert: fp32 -> fp16 transposed panels + norms ----------------
// blocks 0..255: latent panels; 256..271: embedding panels (scaled x2048).
#define QST 136   // smem stride (halves): 272B, 16B-aligned rows
#define QUANT_SMEM (256 * QST * 2)

__global__ void vq_quant_kernel(const float* __restrict__ latents,
                                const float* __restrict__ embedding) {
    extern __shared__ __half Qs[];
    const int tid = threadIdx.x;
    const int w = tid >> 5, lane = tid & 31;
    const bool isE = blockIdx.x >= 256;
    const int p = isE ? (int)blockIdx.x - 256 : (int)blockIdx.x;
    const float* src = isE ? embedding : latents;
    const float scale = isE ? 2048.0f : 1.0f;

    if (blockIdx.x == 0)
        for (int k = tid; k < K_CODES; k += 256) g_counts[k] = 0;

    for (int it = 0; it < 16; it++) {
        const int rl = it * 8 + w;
        const int row = p * 128 + rl;
        const float4* pr = (const float4*)(src + (size_t)row * D_DIM);
        const float4 f0 = pr[lane];
        const float4 f1 = pr[lane + 32];

        float ss = f0.x*f0.x + f0.y*f0.y + f0.z*f0.z + f0.w*f0.w
                 + f1.x*f1.x + f1.y*f1.y + f1.z*f1.z + f1.w*f1.w;
#pragma unroll
        for (int off = 16; off; off >>= 1)
            ss += __shfl_xor_sync(0xffffffffu, ss, off);
        if (lane == 0) {
            if (isE) g_esq[row] = ss; else g_xsq[row] = ss;
        }

        const float v0[4] = {f0.x, f0.y, f0.z, f0.w};
        const float v1[4] = {f1.x, f1.y, f1.z, f1.w};
#pragma unroll
        for (int q = 0; q < 4; q++) {
            Qs[(lane * 4 + q) * QST + rl]       = __float2half(v0[q] * scale);
            Qs[(128 + lane * 4 + q) * QST + rl] = __float2half(v1[q] * scale);
        }
    }
    __syncthreads();

    __half* dst = (isE ? g_eh : g_xh) + (size_t)p * 32768;
#pragma unroll
    for (int i = 0; i < 16; i++) {
        const int o16 = i * 256 + tid;              // uint4 index (4096 total)
        const int d = o16 >> 4, m = (o16 & 15) * 8;
        *(uint4*)(dst + o16 * 8) = *(const uint4*)(Qs + d * QST + m);
    }
}

// ---------------- main: HFMA2 fp16 GEMM + fused argmin ----------------
#define SMEM_TOTAL 131072   // A 64KB + B 2x32KB

__global__ void __launch_bounds__(256, 1)
vq_main_kernel(float* __restrict__ out) {
    extern __shared__ __half smh[];
    const uint32_t smb = smem_to_u32(smh);

    const int tid  = threadIdx.x;
    const int r    = tid >> 4;     // 0..15: rows r*8..+7
    const int c    = tid & 15;     // 0..15: cols c*8..+7 (within jn tile)
    const int lane = tid & 31;
    const int row0 = blockIdx.x * 128;

    // A panel: contiguous 64KB
    {
        const char* gA = (const char*)(g_xh + (size_t)blockIdx.x * 32768);
#pragma unroll
        for (int i = 0; i < 16; i++)
            cpa16(smb + (tid + i * 256) * 16, gA + (tid + i * 256) * 16);
    }
    CP_COMMIT();

    // B chunk s (0..31): jn = s>>1, d-half = s&1, 32KB each
    auto loadB = [&](int s) {
        const char* gB = (const char*)(g_eh + (size_t)(s >> 1) * 32768 + (s & 1) * 16384);
        const uint32_t db = smb + 65536 + (s & 1) * 32768;
#pragma unroll
        for (int i = 0; i < 8; i++)
            cpa16(db + (tid + i * 256) * 16, gB + (tid + i * 256) * 16);
    };
    loadB(0); CP_COMMIT();
    loadB(1); CP_COMMIT();

    float rb[8], rb2[8];
    int   ri[8];
#pragma unroll
    for (int i = 0; i < 8; i++) { rb[i] = 3.0e38f; rb2[i] = 3.0e38f; ri[i] = 0; }

    for (int jn = 0; jn < 16; jn++) {
        float accf[8][8];
#pragma unroll
        for (int i = 0; i < 8; i++)
#pragma unroll
            for (int j = 0; j < 8; j++) accf[i][j] = 0.0f;

#pragma unroll 1
        for (int h = 0; h < 2; h++) {
            const int s = jn * 2 + h;
            CP_WAIT1();
            __syncthreads();
            const __half* A  = smh + h * 16384;                    // d-half of panel
            const __half* Bc = smh + 32768 + (s & 1) * 16384;

#pragma unroll 1
            for (int g = 0; g < 8; g++) {                          // 8 groups of 16 k
                __half2 acch[8][4];
#pragma unroll
                for (int i = 0; i < 8; i++)
#pragma unroll
                    for (int jp = 0; jp < 4; jp++)
                        acch[i][jp] = __floats2half2_rn(0.0f, 0.0f);

#pragma unroll
                for (int kk = 0; kk < 16; kk++) {
                    const int k = g * 16 + kk;
                    const uint4 a4 = *(const uint4*)(A + k * 128 + r * 8);
                    const uint4 b4 = *(const uint4*)(Bc + k * 128 + c * 8);
                    const uint32_t ar[4] = {a4.x, a4.y, a4.z, a4.w};
                    const uint32_t br[4] = {b4.x, b4.y, b4.z, b4.w};
                    uint32_t ad[8];
#pragma unroll
                    for (int q = 0; q < 4; q++) {
                        ad[2*q]   = __byte_perm(ar[q], ar[q], 0x1010);  // (h0,h0)
                        ad[2*q+1] = __byte_perm(ar[q], ar[q], 0x3232);  // (h1,h1)
                    }
#pragma unroll
                    for (int i = 0; i < 8; i++)
#pragma unroll
                        for (int jp = 0; jp < 4; jp++)
                            acch[i][jp] = __hfma2(u32h2(ad[i]), u32h2(br[jp]),
                                                  acch[i][jp]);
                }
                // drain fp16 -> fp32
#pragma unroll
                for (int i = 0; i < 8; i++)
#pragma unroll
                    for (int jp = 0; jp < 4; jp++) {
                        const float2 f = __half22float2(acch[i][jp]);
                        accf[i][2*jp]   += f.x;
                        accf[i][2*jp+1] += f.y;
                    }
            }
            __syncthreads();
            if (s + 2 < 32) loadB(s + 2);
            CP_COMMIT();
        }

        // epilogue: score = esq - (2/2048)*dot_scaled; running two-smallest
        const int n0 = jn * 128 + c * 8;
        const float4 e0 = *(const float4*)(g_esq + n0);
        const float4 e1 = *(const float4*)(g_esq + n0 + 4);
        const float ev[8] = {e0.x, e0.y, e0.z, e0.w, e1.x, e1.y, e1.z, e1.w};
#pragma unroll
        for (int j = 0; j < 8; j++)
#pragma unroll
            for (int i = 0; i < 8; i++) {
                const float sc = fmaf(-CS, accf[i][j], ev[j]);
                upd1(rb[i], rb2[i], ri[i], sc, n0 + j);
            }
    }

    // merge across the 16 c-threads sharing each row (lane bits 0..3)
#pragma unroll
    for (int i = 0; i < 8; i++)
#pragma unroll
        for (int m = 1; m <= 8; m <<= 1) {
            const float ob  = __shfl_xor_sync(0xffffffffu, rb[i],  m);
            const float ob2 = __shfl_xor_sync(0xffffffffu, rb2[i], m);
            const int   oi  = __shfl_xor_sync(0xffffffffu, ri[i],  m);
            merge2(rb[i], rb2[i], ri[i], ob, ob2, oi);
        }

    if ((lane & 15) == 0) {
#pragma unroll
        for (int i = 0; i < 8; i++) {
            const int row = row0 + r * 8 + i;
            g_ind[row] = ri[i];
            out[OFF_IND + row] = (float)ri[i];
            g_cl_val[row] = g_xsq[row] + rb[i];
            g_flag[row] = (rb2[i] - rb[i] < TIE_EPS) ? 1 : 0;
        }
    }
}

// ---------------- fixup: exact fp32 recompute of ambiguous rows ----------------
__global__ void vq_fixup_kernel(const float* __restrict__ latents,
                                const float* __restrict__ embedding,
                                float* __restrict__ out) {
    __shared__ float lx[256];
    __shared__ float sv[256];
    __shared__ int   si[256];
    const int tid = threadIdx.x;
    const int rbeg = blockIdx.x * 256;

    for (int rr = rbeg; rr < rbeg + 256; rr++) {
        if (!g_flag[rr]) continue;

        lx[tid] = latents[(size_t)rr * D_DIM + tid];
        __syncthreads();
        const float xq = g_xsq[rr];
        float bb = 3.0e38f;
        int bi = 0x7fffffff;
#pragma unroll
        for (int cc = 0; cc < 8; cc++) {
            const int cI = cc * 256 + tid;
            const float* e = embedding + (size_t)cI * D_DIM;
            float dot = 0.0f;
#pragma unroll 8
            for (int k = 0; k < D_DIM; k++) dot = fmaf(e[k], lx[k], dot);
            const float sc = (xq + g_esq[cI]) - 2.0f * dot;
            if (sc < bb || (sc == bb && cI < bi)) { bb = sc; bi = cI; }
        }
        sv[tid] = bb; si[tid] = bi;
        __syncthreads();
        for (int o = 128; o; o >>= 1) {
            if (tid < o) {
                const float v2 = sv[tid + o]; const int i2 = si[tid + o];
                if (v2 < sv[tid] || (v2 == sv[tid] && i2 < si[tid])) { sv[tid] = v2; si[tid] = i2; }
            }
            __syncthreads();
        }
        if (tid == 0) {
            g_ind[rr] = si[0];
            out[OFF_IND + rr] = (float)si[0];
            g_cl_val[rr] = sv[0];
        }
        __syncthreads();
    }
}

// ---------------- gather + straight-through + mse partials + histogram ----------------
__global__ void vq_gather_kernel(const float* __restrict__ latents,
                                 const float* __restrict__ embedding,
                                 float* __restrict__ out) {
    const int i4 = blockIdx.x * blockDim.x + threadIdx.x;   // float4 index
    const int b  = i4 >> 6;
    const int d  = (i4 & 63) << 2;
    const int ind = g_ind[b];

    if ((i4 & 63) == 0) atomicAdd(&g_counts[ind], 1);

    const float4 q = *reinterpret_cast<const float4*>(embedding + (size_t)ind * D_DIM + d);
    const float4 x = *reinterpret_cast<const float4*>(latents + (size_t)b * D_DIM + d);

    const float dx = q.x - x.x, dy = q.y - x.y, dz = q.z - x.z, dw = q.w - x.w;
    float4 o;
    o.x = x.x + dx; o.y = x.y + dy; o.z = x.z + dz; o.w = x.w + dw;
    *reinterpret_cast<float4*>(out + (size_t)i4 * 4) = o;

    float ss = dx*dx + dy*dy + dz*dz + dw*dw;
#pragma unroll
    for (int off = 16; off; off >>= 1)
        ss += __shfl_down_sync(0xffffffffu, ss, off);

    __shared__ float w[8];
    const int lane = threadIdx.x & 31;
    const int warp = threadIdx.x >> 5;
    if (lane == 0) w[warp] = ss;
    __syncthreads();
    if (threadIdx.x == 0) {
        float t = 0.0f;
        for (int i = 0; i < 8; i++) t += w[i];
        g_mse_part[blockIdx.x] = t;
    }
}

// ---------------- finalize scalars ----------------
__global__ void vq_finalize_kernel(float* __restrict__ out) {
    __shared__ float sh[256];
    const int tid = threadIdx.x;

    float s = 0.0f;
    for (int i = tid; i < 8192; i += 256) s += g_mse_part[i];
    sh[tid] = s; __syncthreads();
    for (int o = 128; o; o >>= 1) { if (tid < o) sh[tid] += sh[tid + o]; __syncthreads(); }
    const float mse_sum = sh[0];
    __syncthreads();

    s = 0.0f;
    for (int i = tid; i < B_ROWS; i += 256) s += g_cl_val[i];
    sh[tid] = s; __syncthreads();
    for (int o = 128; o; o >>= 1) { if (tid < o) sh[tid] += sh[tid + o]; __syncthreads(); }
    const float cl_sum = sh[0];
    __syncthreads();

    s = 0.0f;
    for (int k = tid; k < K_CODES; k += 256) {
        const float p = (float)g_counts[k] * (1.0f / 32768.0f);
        s += p * logf(p + 1e-10f);
    }
    sh[tid] = s; __syncthreads();
    for (int o = 128; o; o >>= 1) { if (tid < o) sh[tid] += sh[tid + o]; __syncthreads(); }

    if (tid == 0) {
        const float m = mse_sum / 8388608.0f;
        out[OFF_VQ]  = m * 0.25f + m;
        out[OFF_ENT] = -sh[0];
        out[OFF_CL]  = cl_sum / 32768.0f;
    }
}

extern "C" void kernel_launch(void* const* d_in, const int* in_sizes, int n_in,
                              void* d_out, int out_size) {
    const float* latents   = (const float*)d_in[0];
    const float* embedding = (const float*)d_in[1];
    float* out = (float*)d_out;

    cudaFuncSetAttribute(vq_quant_kernel,
                         cudaFuncAttributeMaxDynamicSharedMemorySize, QUANT_SMEM);
    cudaFuncSetAttribute(vq_main_kernel,
                         cudaFuncAttributeMaxDynamicSharedMemorySize, SMEM_TOTAL);

    vq_quant_kernel<<<272, 256, QUANT_SMEM>>>(latents, embedding);
    vq_main_kernel<<<B_ROWS / 128, 256, SMEM_TOTAL>>>(out);
    vq_fixup_kernel<<<B_ROWS / 256, 256>>>(latents, embedding, out);
    vq_gather_kernel<<<(B_ROWS * D_DIM) / (256 * 4), 256>>>(latents, embedding, out);
    vq_finalize_kernel<<<1, 256>>>(out);
}

// round 8
// speedup vs baseline: 5.1002x; 2.1654x over previous
#include <cuda_runtime.h>
#include <cstdint>

#define B_ROWS  32768
#define D_DIM   256
#define K_CODES 2048

// output layout (float32): quantized_st[B*D], vq_loss, entropy, inds[B], cluster_metric
#define OFF_VQ  8388608
#define OFF_ENT 8388609
#define OFF_IND 8388610
#define OFF_CL  8421378

#define TIE_EPS 6.104e-5f   // 2 ulp of ~256-scale scores: exact-tie safety window

// ---------------- device scratch ----------------
__device__ float g_xt[B_ROWS * D_DIM];       // [256 panels][256 k][128 rows]
__device__ float g_et[K_CODES * D_DIM * 2];  // [16 panels][256 k][256 dup slots]
__device__ float g_xsq[B_ROWS];
__device__ float g_esq[K_CODES];
__device__ float g_pb [4 * B_ROWS];          // per-quarter partials
__device__ float g_pb2[4 * B_ROWS];
__device__ int   g_pi [4 * B_ROWS];
__device__ int   g_ind[B_ROWS];
__device__ int   g_flag[B_ROWS];
__device__ float g_cl_val[B_ROWS];
__device__ int   g_counts[K_CODES];
__device__ float g_mse_part[8192];

// ---------------- helpers ----------------
__device__ __forceinline__ uint32_t smem_to_u32(const void* p) {
    uint32_t a;
    asm("{ .reg .u64 t; cvta.to.shared.u64 t, %1; cvt.u32.u64 %0, t; }"
        : "=r"(a) : "l"(p));
    return a;
}
__device__ __forceinline__ void cpa16(uint32_t dst, const void* src) {
    asm volatile("cp.async.cg.shared.global [%0], [%1], 16;"
        :: "r"(dst), "l"((unsigned long long)__cvta_generic_to_global(src)) : "memory");
}
#define CP_COMMIT() asm volatile("cp.async.commit_group;" ::: "memory")
#define CP_WAIT1()  asm volatile("cp.async.wait_group 1;" ::: "memory")

__device__ __forceinline__ void ffma2(unsigned long long &d, unsigned long long a,
                                      unsigned long long b) {
    asm("fma.rn.f32x2 %0, %1, %2, %0;" : "+l"(d) : "l"(a), "l"(b));
}
__device__ __forceinline__ void unpack_f32x2(unsigned long long v, float &lo, float &hi) {
    asm("mov.b64 {%0, %1}, %2;" : "=f"(lo), "=f"(hi) : "l"(v));
}

// two-smallest tracking with first-index tie-break (matches jnp.argmin)
__device__ __forceinline__ void upd1(float& b, float& b2, int& i, float v, int n) {
    if (v < b || (v == b && n < i)) { b2 = b; b = v; i = n; }
    else b2 = fminf(b2, v);
}
__device__ __forceinline__ void merge2(float& b, float& b2, int& i,
                                       float ob, float ob2, int oi) {
    if (ob < b || (ob == b && oi < i)) { b2 = fminf(b, ob2); b = ob; i = oi; }
    else b2 = fminf(b2, ob);
}

// ---------------- prep X: transpose latents panels + xsq + zero hist ----------------
#define PREPX_SMEM (132 * 128 * 4)   // [128 k][132 rows padded] fp32

__global__ void vq_prep_x(const float* __restrict__ latents) {
    extern __shared__ float Qs[];
    const int tid = threadIdx.x;
    const int p = blockIdx.x;
    const int row = tid >> 1;
    const int fbase = (tid & 1) * 16;
    float xacc = 0.0f;

    if (p == 0)
        for (int k = tid; k < K_CODES; k += 256) g_counts[k] = 0;

    for (int h = 0; h < 2; h++) {
        const float4* src = (const float4*)(latents
                            + (size_t)(p * 128 + row) * D_DIM + h * 128);
#pragma unroll
        for (int q = 0; q < 16; q++) {
            const float4 v = src[fbase + q];
            xacc += v.x*v.x + v.y*v.y + v.z*v.z + v.w*v.w;
            const int k = (fbase + q) * 4;
            Qs[(k + 0) * 132 + row] = v.x;
            Qs[(k + 1) * 132 + row] = v.y;
            Qs[(k + 2) * 132 + row] = v.z;
            Qs[(k + 3) * 132 + row] = v.w;
        }
        __syncthreads();
        float* dst = g_xt + ((size_t)p * 256 + h * 128) * 128;
#pragma unroll
        for (int it = 0; it < 16; it++) {
            const int idx = it * 256 + tid;
            const int k = idx >> 5, r4 = (idx & 31) * 4;
            *(float4*)(dst + k * 128 + r4) = *(const float4*)(Qs + k * 132 + r4);
        }
        __syncthreads();
    }
    xacc += __shfl_xor_sync(0xffffffffu, xacc, 1);
    if ((tid & 1) == 0) g_xsq[p * 128 + row] = xacc;
}

// ---------------- prep E: duplicated transposed embedding + esq ----------------
// slot layout per k (256 floats): granule (c,j) at j*64 + c*4 holds cols
// n0 = c*8+2j (dup at +0,+1) and n0+1 (dup at +2,+3).
__global__ void vq_prep_e(const float* __restrict__ embedding) {
    const int tid = threadIdx.x;
    const int w = tid >> 5, lane = tid & 31;
    const int n = blockIdx.x * 8 + w;       // 0..2047
    const int jn = n >> 7;
    const int nn = n & 127;
    const int c = nn >> 3, jj = (nn & 7) >> 1, t = nn & 1;
    float* base = g_et + (size_t)jn * 65536 + jj * 64 + c * 4 + t * 2;

    const float4* src = (const float4*)(embedding + (size_t)n * D_DIM);
    float ss = 0.0f;
#pragma unroll
    for (int q = 0; q < 2; q++) {
        const int f4i = lane + q * 32;
        const float4 v = src[f4i];
        ss += v.x*v.x + v.y*v.y + v.z*v.z + v.w*v.w;
        const int k = f4i * 4;
        *(float2*)(base + (size_t)(k + 0) * 256) = make_float2(v.x, v.x);
        *(float2*)(base + (size_t)(k + 1) * 256) = make_float2(v.y, v.y);
        *(float2*)(base + (size_t)(k + 2) * 256) = make_float2(v.z, v.z);
        *(float2*)(base + (size_t)(k + 3) * 256) = make_float2(v.w, v.w);
    }
#pragma unroll
    for (int off = 16; off; off >>= 1)
        ss += __shfl_xor_sync(0xffffffffu, ss, off);
    if (lane == 0) g_esq[n] = ss;
}

// ---------------- main: pure-FFMA2 GEMM + fused argmin ----------------
// unit = (panel, col-quarter): 128 rows x 512 cols. Grid 1024.
#define SMEM_TOTAL 196608   // A 128KB resident + B 2x32KB double-buffered

__global__ void __launch_bounds__(256, 1)
vq_main_kernel() {
    extern __shared__ float smf[];
    const uint32_t smb = smem_to_u32(smf);

    const int tid  = threadIdx.x;
    const int r    = tid >> 4;    // 0..15: rows r*8..+7
    const int c    = tid & 15;    // 0..15: cols c*8..+7 within jn tile
    const int lane = tid & 31;
    const int panel = blockIdx.x >> 2, quarter = blockIdx.x & 3;
    const int row0 = panel * 128;
    const int jn0 = quarter * 4;

    // A panel: contiguous 128KB
    {
        const char* gA = (const char*)(g_xt + (size_t)panel * 32768);
#pragma unroll
        for (int i = 0; i < 32; i++)
            cpa16(smb + (tid + i * 256) * 16, gA + (tid + i * 256) * 16);
    }
    CP_COMMIT();

    // B chunk s (0..31): jn = jn0 + (s>>3), kc = s&7; 32KB each
    auto loadB = [&](int s) {
        const int jn = jn0 + (s >> 3), kc = s & 7;
        const char* gB = (const char*)(g_et + (size_t)jn * 65536 + kc * 8192);
        const uint32_t db = smb + 131072 + (s & 1) * 32768;
#pragma unroll
        for (int i = 0; i < 8; i++)
            cpa16(db + (tid + i * 256) * 16, gB + (tid + i * 256) * 16);
    };
    loadB(0); CP_COMMIT();
    loadB(1); CP_COMMIT();

    float xq[8];
#pragma unroll
    for (int i = 0; i < 8; i++) xq[i] = g_xsq[row0 + r * 8 + i];

    float rb[8], rb2[8];
    int   ri[8];
#pragma unroll
    for (int i = 0; i < 8; i++) { rb[i] = 3.0e38f; rb2[i] = 3.0e38f; ri[i] = 0; }

    for (int jt = 0; jt < 4; jt++) {
        unsigned long long acc[4][8];
#pragma unroll
        for (int pp = 0; pp < 4; pp++)
#pragma unroll
            for (int m = 0; m < 8; m++) acc[pp][m] = 0ULL;

        for (int kc = 0; kc < 8; kc++) {
            const int s = jt * 8 + kc;
            CP_WAIT1();
            __syncthreads();
            const float* Bb = smf + 32768 + (s & 1) * 8192;

#pragma unroll 4
            for (int kk = 0; kk < 32; kk++) {
                const float* Ak = smf + (kc * 32 + kk) * 128 + r * 8;
                const ulonglong2 a01 = *(const ulonglong2*)Ak;
                const ulonglong2 a23 = *(const ulonglong2*)(Ak + 4);
                const float* Bk = Bb + kk * 256 + c * 4;
                const ulonglong2 b0 = *(const ulonglong2*)(Bk);
                const ulonglong2 b1 = *(const ulonglong2*)(Bk + 64);
                const ulonglong2 b2 = *(const ulonglong2*)(Bk + 128);
                const ulonglong2 b3 = *(const ulonglong2*)(Bk + 192);
                const unsigned long long av[4] = {a01.x, a01.y, a23.x, a23.y};
                const unsigned long long bv[8] = {b0.x, b0.y, b1.x, b1.y,
                                                  b2.x, b2.y, b3.x, b3.y};
#pragma unroll
                for (int pp = 0; pp < 4; pp++)
#pragma unroll
                    for (int m = 0; m < 8; m++)
                        ffma2(acc[pp][m], av[pp], bv[m]);
            }
            __syncthreads();
            if (s + 2 < 32) loadB(s + 2);
            CP_COMMIT();
        }

        // epilogue: score = (xsq + esq) - 2*dot (same chain/shape as reference)
        const int n0 = (jn0 + jt) * 128 + c * 8;
        const float4 e0 = *(const float4*)(g_esq + n0);
        const float4 e1 = *(const float4*)(g_esq + n0 + 4);
        const float ev[8] = {e0.x, e0.y, e0.z, e0.w, e1.x, e1.y, e1.z, e1.w};
#pragma unroll
        for (int m = 0; m < 8; m++)
#pragma unroll
            for (int pp = 0; pp < 4; pp++) {
                float dlo, dhi;
                unpack_f32x2(acc[pp][m], dlo, dhi);
                const float slo = (xq[2*pp]     + ev[m]) - 2.0f * dlo;
                const float shi = (xq[2*pp + 1] + ev[m]) - 2.0f * dhi;
                upd1(rb[2*pp],     rb2[2*pp],     ri[2*pp],     slo, n0 + m);
                upd1(rb[2*pp + 1], rb2[2*pp + 1], ri[2*pp + 1], shi, n0 + m);
            }
    }

    // merge across the 16 c-threads sharing each row (lane bits 0..3)
#pragma unroll
    for (int i = 0; i < 8; i++)
#pragma unroll
        for (int m = 1; m <= 8; m <<= 1) {
            const float ob  = __shfl_xor_sync(0xffffffffu, rb[i],  m);
            const float ob2 = __shfl_xor_sync(0xffffffffu, rb2[i], m);
            const int   oi  = __shfl_xor_sync(0xffffffffu, ri[i],  m);
            merge2(rb[i], rb2[i], ri[i], ob, ob2, oi);
        }

    if ((lane & 15) == 0) {
#pragma unroll
        for (int i = 0; i < 8; i++) {
            const int row = row0 + r * 8 + i;
            g_pb [quarter * B_ROWS + row] = rb[i];
            g_pb2[quarter * B_ROWS + row] = rb2[i];
            g_pi [quarter * B_ROWS + row] = ri[i];
        }
    }
}

// ---------------- merge quarters ----------------
__global__ void vq_merge_kernel(float* __restrict__ out) {
    const int row = blockIdx.x * 256 + threadIdx.x;
    float b = g_pb[row], b2 = g_pb2[row];
    int i = g_pi[row];
#pragma unroll
    for (int q = 1; q < 4; q++)
        merge2(b, b2, i, g_pb[q * B_ROWS + row], g_pb2[q * B_ROWS + row],
               g_pi[q * B_ROWS + row]);
    g_ind[row] = i;
    out[OFF_IND + row] = (float)i;
    g_cl_val[row] = b;
    g_flag[row] = (b2 - b < TIE_EPS) ? 1 : 0;
}

// ---------------- fixup: exact fp32 recompute of ambiguous rows ----------------
__global__ void vq_fixup_kernel(const float* __restrict__ latents,
                                const float* __restrict__ embedding,
                                float* __restrict__ out) {
    __shared__ float lx[256];
    __shared__ float sv[256];
    __shared__ int   si[256];
    const int tid = threadIdx.x;
    const int rbeg = blockIdx.x * 256;

    for (int rr = rbeg; rr < rbeg + 256; rr++) {
        if (!g_flag[rr]) continue;

        lx[tid] = latents[(size_t)rr * D_DIM + tid];
        __syncthreads();
        const float xqv = g_xsq[rr];
        float bb = 3.0e38f;
        int bi = 0x7fffffff;
#pragma unroll
        for (int cc = 0; cc < 8; cc++) {
            const int cI = cc * 256 + tid;
            const float* e = embedding + (size_t)cI * D_DIM;
            float dot = 0.0f;
#pragma unroll 8
            for (int k = 0; k < D_DIM; k++) dot = fmaf(e[k], lx[k], dot);
            const float sc = (xqv + g_esq[cI]) - 2.0f * dot;
            if (sc < bb || (sc == bb && cI < bi)) { bb = sc; bi = cI; }
        }
        sv[tid] = bb; si[tid] = bi;
        __syncthreads();
        for (int o = 128; o; o >>= 1) {
            if (tid < o) {
                const float v2 = sv[tid + o]; const int i2 = si[tid + o];
                if (v2 < sv[tid] || (v2 == sv[tid] && i2 < si[tid])) { sv[tid] = v2; si[tid] = i2; }
            }
            __syncthreads();
        }
        if (tid == 0) {
            g_ind[rr] = si[0];
            out[OFF_IND + rr] = (float)si[0];
            g_cl_val[rr] = sv[0];
        }
        __syncthreads();
    }
}

// ---------------- gather + straight-through + mse partials + histogram ----------------
__global__ void vq_gather_kernel(const float* __restrict__ latents,
                                 const float* __restrict__ embedding,
                                 float* __restrict__ out) {
    const int i4 = blockIdx.x * blockDim.x + threadIdx.x;   // float4 index
    const int b  = i4 >> 6;
    const int d  = (i4 & 63) << 2;
    const int ind = g_ind[b];

    if ((i4 & 63) == 0) atomicAdd(&g_counts[ind], 1);

    const float4 q = *reinterpret_cast<const float4*>(embedding + (size_t)ind * D_DIM + d);
    const float4 x = *reinterpret_cast<const float4*>(latents + (size_t)b * D_DIM + d);

    const float dx = q.x - x.x, dy = q.y - x.y, dz = q.z - x.z, dw = q.w - x.w;
    float4 o;
    o.x = x.x + dx; o.y = x.y + dy; o.z = x.z + dz; o.w = x.w + dw;
    *reinterpret_cast<float4*>(out + (size_t)i4 * 4) = o;

    float ss = dx*dx + dy*dy + dz*dz + dw*dw;
#pragma unroll
    for (int off = 16; off; off >>= 1)
        ss += __shfl_down_sync(0xffffffffu, ss, off);

    __shared__ float w[8];
    const int lane = threadIdx.x & 31;
    const int warp = threadIdx.x >> 5;
    if (lane == 0) w[warp] = ss;
    __syncthreads();
    if (threadIdx.x == 0) {
        float t = 0.0f;
        for (int i = 0; i < 8; i++) t += w[i];
        g_mse_part[blockIdx.x] = t;
    }
}

// ---------------- finalize scalars ----------------
__global__ void vq_finalize_kernel(float* __restrict__ out) {
    __shared__ float sh[256];
    const int tid = threadIdx.x;

    float s = 0.0f;
    for (int i = tid; i < 8192; i += 256) s += g_mse_part[i];
    sh[tid] = s; __syncthreads();
    for (int o = 128; o; o >>= 1) { if (tid < o) sh[tid] += sh[tid + o]; __syncthreads(); }
    const float mse_sum = sh[0];
    __syncthreads();

    s = 0.0f;
    for (int i = tid; i < B_ROWS; i += 256) s += g_cl_val[i];
    sh[tid] = s; __syncthreads();
    for (int o = 128; o; o >>= 1) { if (tid < o) sh[tid] += sh[tid + o]; __syncthreads(); }
    const float cl_sum = sh[0];
    __syncthreads();

    s = 0.0f;
    for (int k = tid; k < K_CODES; k += 256) {
        const float p = (float)g_counts[k] * (1.0f / 32768.0f);
        s += p * logf(p + 1e-10f);
    }
    sh[tid] = s; __syncthreads();
    for (int o = 128; o; o >>= 1) { if (tid < o) sh[tid] += sh[tid + o]; __syncthreads(); }

    if (tid == 0) {
        const float m = mse_sum / 8388608.0f;
        out[OFF_VQ]  = m * 0.25f + m;
        out[OFF_ENT] = -sh[0];
        out[OFF_CL]  = cl_sum / 32768.0f;
    }
}

extern "C" void kernel_launch(void* const* d_in, const int* in_sizes, int n_in,
                              void* d_out, int out_size) {
    const float* latents   = (const float*)d_in[0];
    const float* embedding = (const float*)d_in[1];
    float* out = (float*)d_out;

    cudaFuncSetAttribute(vq_prep_x,
                         cudaFuncAttributeMaxDynamicSharedMemorySize, PREPX_SMEM);
    cudaFuncSetAttribute(vq_main_kernel,
                         cudaFuncAttributeMaxDynamicSharedMemorySize, SMEM_TOTAL);

    vq_prep_x<<<256, 256, PREPX_SMEM>>>(latents);
    vq_prep_e<<<256, 256>>>(embedding);
    vq_main_kernel<<<1024, 256, SMEM_TOTAL>>>();
    vq_merge_kernel<<<B_ROWS / 256, 256>>>(out);
    vq_fixup_kernel<<<B_ROWS / 256, 256>>>(latents, embedding, out);
    vq_gather_kernel<<<(B_ROWS * D_DIM) / (256 * 4), 256>>>(latents, embedding, out);
    vq_finalize_kernel<<<1, 256>>>(out);
}